// round 14
// baseline (speedup 1.0000x reference)
#include <cuda_runtime.h>
#include <cuda.h>
#include <cuda_fp16.h>
#include <cstdint>

// ==================== problem constants ====================
static constexpr int BDIM = 16384;
static constexpr int NIN  = 4096;
static constexpr int NOUT = 4096;

// ==================== GEMM tiling ====================
static constexpr int BM = 128;
static constexpr int BN = 128;
static constexpr int BK = 128;            // fp8 elements of K per stage
static constexpr int STAGES = 3;
static constexpr int KITERS = NIN / BK;   // 32
static constexpr int NXT = NOUT / BN;     // 32 N-tiles (fast axis)
static constexpr int NTILES = (BDIM / BM) * NXT;  // 4096

// smem layout (dynamic)
static constexpr unsigned SM_BARS  = 0;   // full[s] at 8s; empty[s] at 8*(STAGES+s)
static constexpr unsigned SM_TILE0 = 1024;                  // 1024-aligned tiles
static constexpr unsigned A_BYTES     = BM * BK;            // 16384
static constexpr unsigned B_BYTES     = BN * BK;            // 16384
static constexpr unsigned STAGE_BYTES = A_BYTES + B_BYTES;  // 32768
static constexpr unsigned SMEM_TOTAL  = SM_TILE0 + STAGES * STAGE_BYTES; // 99328 (2 CTAs/SM)

static constexpr int MATH_WARPS = 8;
static constexpr int NTHREADS   = (MATH_WARPS + 1) * 32;    // 288: 8 math + 1 producer

// merged prep grid: blocks [0, NOUT) do weight rows; [NOUT, NOUT + XBLOCKS) do x chunks
static constexpr int XBLOCKS = BDIM * NIN / 16 / 256;       // 16384

// ==================== scratch (device globals: no allocs allowed) ====================
__device__ __align__(1024) unsigned char g_xb[(size_t)BDIM * NIN]; // sign(x) as e4m3
__device__ __align__(1024) unsigned char g_wb[(size_t)NOUT * NIN]; // sign(fp-mean) as e4m3
__device__ float g_scale[NOUT];

// ==================== PTX helpers (baseline PTX only) ====================
__device__ __forceinline__ uint32_t smem_to_u32(const void* p) {
    uint32_t a;
    asm("{ .reg .u64 t; cvta.to.shared.u64 t, %1; cvt.u32.u64 %0, t; }" : "=r"(a) : "l"(p));
    return a;
}

#define MBARRIER_INIT(addr, cnt) \
    asm volatile("mbarrier.init.shared.b64 [%0], %1;" :: "r"((uint32_t)(addr)), "r"((uint32_t)(cnt)) : "memory")

#define MBARRIER_ARRIVE(addr) \
    asm volatile("mbarrier.arrive.shared.b64 _, [%0];" :: "r"((uint32_t)(addr)) : "memory")

#define MBARRIER_EXPECT_TX(addr, bytes) \
    asm volatile("mbarrier.arrive.expect_tx.shared.b64 _, [%0], %1;" :: "r"((uint32_t)(addr)), "r"((uint32_t)(bytes)) : "memory")

#define MBARRIER_WAIT_PARITY(mbar_smem_addr, phase_parity) do { \
    uint32_t _mbar = (uint32_t)(mbar_smem_addr); \
    uint32_t _parity = (uint32_t)(phase_parity); \
    uint32_t _done; \
    asm volatile( \
        "{\n\t.reg .pred p;\n\t" \
        "mbarrier.try_wait.parity.acquire.cta.shared::cta.b64 p, [%1], %2;\n\t" \
        "selp.b32 %0, 1, 0, p;\n\t}" \
        : "=r"(_done) : "r"(_mbar), "r"(_parity) : "memory"); \
    if (!_done) { \
        asm volatile( \
            "{\n\t.reg .pred P1;\n\t" \
            "WAIT_LOOP_%=:\n\t" \
            "mbarrier.try_wait.parity.acquire.cta.shared::cta.b64 P1, [%0], %1, 0x989680;\n\t" \
            "@P1 bra.uni WAIT_DONE_%=;\n\t" \
            "bra.uni WAIT_LOOP_%=;\n\t" \
            "WAIT_DONE_%=:\n\t}" \
            :: "r"(_mbar), "r"(_parity) : "memory"); \
    } \
} while (0)

#define TMA_LOAD_3D(smem_addr, tensor_map, cx, cy, cz, mbar) \
    asm volatile( \
        "cp.async.bulk.tensor.3d.shared::cta.global.tile.mbarrier::complete_tx::bytes " \
        "[%0], [%1, {%2, %3, %4}], [%5];" \
        :: "r"((uint32_t)(smem_addr)), "l"(tensor_map), "r"((int32_t)(cx)), "r"((int32_t)(cy)), \
           "r"((int32_t)(cz)), "r"((uint32_t)(mbar)) : "memory")

#define FENCE_PROXY_ASYNC_SHARED_CTA() asm volatile("fence.proxy.async.shared::cta;" ::: "memory")

#define LDMATRIX_X4(r0, r1, r2, r3, addr) \
    asm volatile("ldmatrix.sync.aligned.m8n8.x4.shared.b16 {%0,%1,%2,%3}, [%4];" \
                 : "=r"(r0), "=r"(r1), "=r"(r2), "=r"(r3) : "r"(addr))

// legacy FP8 QMMA with F16 accumulator: m16n8k32, e4m3 x e4m3 (sm_89+ baseline).
#define MMA_F8_H(d, a, b) \
    asm volatile("mma.sync.aligned.m16n8k32.row.col.f16.e4m3.e4m3.f16 " \
                 "{%0,%1}, {%2,%3,%4,%5}, {%6,%7}, {%0,%1};" \
                 : "+r"((d)[0]), "+r"((d)[1]) \
                 : "r"((a)[0]), "r"((a)[1]), "r"((a)[2]), "r"((a)[3]), \
                   "r"((b)[0]), "r"((b)[1]))

// ==================== merged prep kernel ====================
// e4m3: +1.0 = 0x38, -1.0 = 0xB8, 0.0 = 0x00
__device__ __forceinline__ uint32_t sgn8(float v) {
    return v > 0.f ? 0x38u : (v < 0.f ? 0xB8u : 0x00u);
}

// blocks [0, NOUT): one weight row each (center, clamp, sign, scale).
// blocks [NOUT, NOUT+XBLOCKS): 4096-byte x chunks (sign pack).
__global__ void __launch_bounds__(256) prep_all_kernel(const float4* __restrict__ x,
                                                       uint4* __restrict__ xb,
                                                       const float* __restrict__ w,
                                                       uint4* __restrict__ wb,
                                                       float* __restrict__ scale) {
    const int tid = threadIdx.x;
    if (blockIdx.x >= NOUT) {
        // ---- x path ----
        const size_t i = (size_t)(blockIdx.x - NOUT) * 256 + tid;
        uint32_t p[4];
#pragma unroll
        for (int q = 0; q < 4; q++) {
            float4 v = x[i * 4 + q];
            p[q] = sgn8(v.x) | (sgn8(v.y) << 8) | (sgn8(v.z) << 16) | (sgn8(v.w) << 24);
        }
        xb[i] = make_uint4(p[0], p[1], p[2], p[3]);
        return;
    }

    // ---- w path ----
    __shared__ float red[256];
    const int row = blockIdx.x;
    const float4* wr = (const float4*)(w + (size_t)row * NIN);

    float4 v[4];
    float s = 0.f;
#pragma unroll
    for (int q = 0; q < 4; q++) {
        v[q] = wr[tid * 4 + q];
        s += (v[q].x + v[q].y) + (v[q].z + v[q].w);
    }
    red[tid] = s;
    __syncthreads();
    for (int o = 128; o > 0; o >>= 1) {
        if (tid < o) red[tid] += red[tid + o];
        __syncthreads();
    }
    const float mean = red[0] * (1.f / NIN);
    __syncthreads();

    float a = 0.f;
    uint32_t p[4];
#pragma unroll
    for (int q = 0; q < 4; q++) {
        float f0 = v[q].x - mean, f1 = v[q].y - mean, f2 = v[q].z - mean, f3 = v[q].w - mean;
        a += fabsf(fminf(fmaxf(f0, -1.f), 1.f));
        a += fabsf(fminf(fmaxf(f1, -1.f), 1.f));
        a += fabsf(fminf(fmaxf(f2, -1.f), 1.f));
        a += fabsf(fminf(fmaxf(f3, -1.f), 1.f));
        p[q] = sgn8(f0) | (sgn8(f1) << 8) | (sgn8(f2) << 16) | (sgn8(f3) << 24);
    }
    wb[(size_t)row * (NIN / 16) + tid] = make_uint4(p[0], p[1], p[2], p[3]);

    red[tid] = a;
    __syncthreads();
    for (int o = 128; o > 0; o >>= 1) {
        if (tid < o) red[tid] += red[tid + o];
        __syncthreads();
    }
    if (tid == 0) scale[row] = red[0] * (1.f / NIN);
}

// ==================== GEMM kernel (persistent, legacy FP8 QMMA f16-acc) ====================
// 288 threads: warps 0-7 math (2m x 4n grid, 64x32 warp tile), warp 8 = TMA producer.
// 2 CTAs/SM. Persistent: each CTA loops over tiles (stride gridDim.x); the mbarrier
// ring cursors run continuously across tiles so the producer streams the next tile's
// loads while math warps run the current tile's epilogue. The inner K-loop body is
// byte-identical to the measured optimum (R13).
__global__ void __launch_bounds__(NTHREADS, 2)
xnor_gemm_kernel(const __grid_constant__ CUtensorMap tma_a,
                 const __grid_constant__ CUtensorMap tma_b,
                 const float* __restrict__ scale,
                 const float* __restrict__ bias,
                 float* __restrict__ out) {
    extern __shared__ char smem[];
    const uint32_t sb = smem_to_u32(smem);
    const int tid = threadIdx.x;
    const int wid = tid >> 5;
    const int lane = tid & 31;

    if (tid == 0) {
#pragma unroll
        for (int s = 0; s < STAGES; s++) {
            MBARRIER_INIT(sb + SM_BARS + 8u * s, 1);                    // full (TMA tx)
            MBARRIER_INIT(sb + SM_BARS + 8u * (STAGES + s), MATH_WARPS); // empty
        }
        FENCE_PROXY_ASYNC_SHARED_CTA();
    }
    __syncthreads();  // barriers initialized

    if (wid == MATH_WARPS) {
        // ================= producer warp: continuous stream across tiles =================
        if (lane == 0) {
            int s = 0, eph = 1, loads = 0;  // eph=1 so first wrap lands phase 0
            for (int t = blockIdx.x; t < NTILES; t += gridDim.x) {
                const int tn0 = (t & (NXT - 1)) * BN;
                const int tm0 = (t >> 5) * BM;
                for (int k = 0; k < KITERS; ++k) {
                    if (loads >= STAGES) {
                        MBARRIER_WAIT_PARITY(sb + SM_BARS + 8u * (STAGES + s), eph);
                    }
                    MBARRIER_EXPECT_TX(sb + SM_BARS + 8u * s, STAGE_BYTES);
                    const uint32_t st = sb + SM_TILE0 + (uint32_t)s * STAGE_BYTES;
                    TMA_LOAD_3D(st, &tma_a, k * BK, tm0, 0, sb + SM_BARS + 8u * s);
                    TMA_LOAD_3D(st + A_BYTES, &tma_b, k * BK, tn0, 0, sb + SM_BARS + 8u * s);
                    loads++;
                    if (++s == STAGES) { s = 0; eph ^= 1; }
                }
            }
        }
        return;
    }

    // ================= math warps =================
    const int warp_m = wid & 1;   // 0..1  (64 rows each)
    const int warp_n = wid >> 1;  // 0..3  (32 cols each)
    const int rlo = lane & 7;
    const int sub = (lane >> 3) & 3;

    // precomputed ldmatrix offsets (SW128: phys = row*128 + (kbyte ^ ((row&7)<<4)))
    uint32_t aRow[4], bRow[2], kx[4];
#pragma unroll
    for (int im = 0; im < 4; im++)
        aRow[im] = (uint32_t)(warp_m * 64 + im * 16 + (sub & 1) * 8 + rlo) * 128u;
#pragma unroll
    for (int bp = 0; bp < 2; bp++)
        bRow[bp] = (uint32_t)(warp_n * 32 + bp * 16 + (sub & 1) * 8 + rlo) * 128u;
#pragma unroll
    for (int ks = 0; ks < 4; ks++)
        kx[ks] = (uint32_t)((ks * 32 + ((sub >> 1) & 1) * 16) ^ (rlo << 4));

    int s = 0, ph = 0;  // continuous ring cursor across tiles
    for (int t = blockIdx.x; t < NTILES; t += gridDim.x) {
        const int tn0 = (t & (NXT - 1)) * BN;
        const int tm0 = (t >> 5) * BM;

        // f16x2 accumulators (exact: |partial sums| << 2048)
        uint32_t d[4][4][2];
#pragma unroll
        for (int im = 0; im < 4; im++)
#pragma unroll
            for (int in = 0; in < 4; in++) { d[im][in][0] = 0u; d[im][in][1] = 0u; }

        for (int it = 0; it < KITERS; ++it) {
            MBARRIER_WAIT_PARITY(sb + SM_BARS + 8u * s, ph);
            const uint32_t saA = sb + SM_TILE0 + (uint32_t)s * STAGE_BYTES;
            const uint32_t saB = saA + A_BYTES;

#pragma unroll
            for (int ks = 0; ks < 4; ks++) {
                uint32_t a[4][4];
                uint32_t b[4][2];
#pragma unroll
                for (int im = 0; im < 4; im++) {
                    LDMATRIX_X4(a[im][0], a[im][1], a[im][2], a[im][3], saA + aRow[im] + kx[ks]);
                }
#pragma unroll
                for (int bp = 0; bp < 2; bp++) {
                    uint32_t r0, r1, r2, r3;
                    LDMATRIX_X4(r0, r1, r2, r3, saB + bRow[bp] + kx[ks]);
                    b[2 * bp][0] = r0; b[2 * bp + 1][0] = r1;
                    b[2 * bp][1] = r2; b[2 * bp + 1][1] = r3;
                }
#pragma unroll
                for (int im = 0; im < 4; im++)
#pragma unroll
                    for (int in = 0; in < 4; in++) MMA_F8_H(d[im][in], a[im], b[in]);
            }

            if (lane == 0) MBARRIER_ARRIVE(sb + SM_BARS + 8u * (STAGES + s));
            if (++s == STAGES) { s = 0; ph ^= 1; }
        }

        // -------- epilogue (overlaps producer's next-tile loads) --------
        const int gm0 = tm0 + warp_m * 64 + (lane >> 2);
        const int lc0 = tn0 + warp_n * 32 + (lane & 3) * 2;
#pragma unroll
        for (int im = 0; im < 4; im++) {
#pragma unroll
            for (int in = 0; in < 4; in++) {
                const int lc = lc0 + in * 8;
                const float sc0 = __ldg(scale + lc), sc1 = __ldg(scale + lc + 1);
                const float bi0 = __ldg(bias + lc),  bi1 = __ldg(bias + lc + 1);
                const int row0 = gm0 + im * 16;
                const float2 lo = __half22float2(*reinterpret_cast<const __half2*>(&d[im][in][0]));
                const float2 hi = __half22float2(*reinterpret_cast<const __half2*>(&d[im][in][1]));
                float2 v0, v1;
                v0.x = lo.x * sc0 + bi0;
                v0.y = lo.y * sc1 + bi1;
                v1.x = hi.x * sc0 + bi0;
                v1.y = hi.y * sc1 + bi1;
                *reinterpret_cast<float2*>(out + (size_t)row0 * NOUT + lc) = v0;
                *reinterpret_cast<float2*>(out + (size_t)(row0 + 8) * NOUT + lc) = v1;
            }
        }
    }
}

// ==================== host launch ====================
typedef CUresult (*TMEncodeFn)(CUtensorMap*, CUtensorMapDataType, cuuint32_t, void*,
                               const cuuint64_t*, const cuuint64_t*, const cuuint32_t*,
                               const cuuint32_t*, CUtensorMapInterleave, CUtensorMapSwizzle,
                               CUtensorMapL2promotion, CUtensorMapFloatOOBfill);

extern "C" void kernel_launch(void* const* d_in, const int* in_sizes, int n_in,
                              void* d_out, int out_size) {
    const float* x    = (const float*)d_in[0];
    const float* fp   = (const float*)d_in[1];
    const float* bias = (const float*)d_in[2];
    float* out = (float*)d_out;

    void *xb = nullptr, *wb = nullptr, *scale = nullptr;
    cudaGetSymbolAddress(&xb, g_xb);
    cudaGetSymbolAddress(&wb, g_wb);
    cudaGetSymbolAddress(&scale, g_scale);

    // merged preprocessing: w-rows (blocks 0..4095) + x-chunks (blocks 4096..20479)
    prep_all_kernel<<<NOUT + XBLOCKS, 256>>>((const float4*)x, (uint4*)xb,
                                             fp, (uint4*)wb, (float*)scale);

    // TMA descriptors (driver entry point via runtime — no -lcuda needed)
    TMEncodeFn enc = nullptr;
    cudaDriverEntryPointQueryResult qr;
    cudaGetDriverEntryPoint("cuTensorMapEncodeTiled", (void**)&enc, cudaEnableDefault, &qr);

    CUtensorMap ta, tb;
    cuuint32_t es[3] = {1, 1, 1};
    {
        cuuint64_t dims[3] = {NIN, BDIM, 1};
        cuuint64_t str[2]  = {NIN, (cuuint64_t)NIN * BDIM};
        cuuint32_t box[3]  = {BK, BM, 1};
        enc(&ta, CU_TENSOR_MAP_DATA_TYPE_UINT8, 3, xb, dims, str, box, es,
            CU_TENSOR_MAP_INTERLEAVE_NONE, CU_TENSOR_MAP_SWIZZLE_128B,
            CU_TENSOR_MAP_L2_PROMOTION_L2_128B, CU_TENSOR_MAP_FLOAT_OOB_FILL_NONE);
    }
    {
        cuuint64_t dims[3] = {NIN, NOUT, 1};
        cuuint64_t str[2]  = {NIN, (cuuint64_t)NIN * NOUT};
        cuuint32_t box[3]  = {BK, BN, 1};
        enc(&tb, CU_TENSOR_MAP_DATA_TYPE_UINT8, 3, wb, dims, str, box, es,
            CU_TENSOR_MAP_INTERLEAVE_NONE, CU_TENSOR_MAP_SWIZZLE_128B,
            CU_TENSOR_MAP_L2_PROMOTION_L2_128B, CU_TENSOR_MAP_FLOAT_OOB_FILL_NONE);
    }

    // persistent grid: 2 CTAs per SM, one wave
    int dev = 0, nsm = 148;
    cudaGetDevice(&dev);
    cudaDeviceGetAttribute(&nsm, cudaDevAttrMultiProcessorCount, dev);
    int grid = 2 * nsm;
    if (grid > NTILES) grid = NTILES;

    cudaFuncSetAttribute(xnor_gemm_kernel, cudaFuncAttributeMaxDynamicSharedMemorySize,
                         SMEM_TOTAL);
    xnor_gemm_kernel<<<grid, NTHREADS, SMEM_TOTAL>>>(
        ta, tb, (const float*)scale, bias, out);
}

// round 15
// speedup vs baseline: 1.0199x; 1.0199x over previous
#include <cuda_runtime.h>
#include <cuda.h>
#include <cuda_fp16.h>
#include <cstdint>

// ==================== problem constants ====================
static constexpr int BDIM = 16384;
static constexpr int NIN  = 4096;
static constexpr int NOUT = 4096;

// ==================== GEMM tiling ====================
static constexpr int BM = 128;
static constexpr int BN = 128;
static constexpr int BK = 128;            // fp8 elements of K per stage
static constexpr int STAGES = 3;
static constexpr int KITERS = NIN / BK;   // 32

// smem layout (dynamic)
static constexpr unsigned SM_BARS  = 0;   // full[s] at 8s; empty[s] at 8*(STAGES+s)
static constexpr unsigned SM_SC    = 128;                   // BN floats (scale)
static constexpr unsigned SM_BI    = SM_SC + BN * 4;
static constexpr unsigned SM_TILE0 = 4096;                  // 1024-aligned tiles
static constexpr unsigned A_BYTES     = BM * BK;            // 16384
static constexpr unsigned B_BYTES     = BN * BK;            // 16384
static constexpr unsigned STAGE_BYTES = A_BYTES + B_BYTES;  // 32768
static constexpr unsigned SMEM_TOTAL  = SM_TILE0 + STAGES * STAGE_BYTES; // 102400 (2 CTAs/SM)

static constexpr int MATH_WARPS = 8;
static constexpr int NTHREADS   = (MATH_WARPS + 1) * 32;    // 288: 8 math + 1 producer

// merged prep grid: blocks [0, NOUT) do weight rows; [NOUT, NOUT + XBLOCKS) do x chunks
static constexpr int XBLOCKS = BDIM * NIN / 16 / 256;       // 16384

// ==================== scratch (device globals: no allocs allowed) ====================
__device__ __align__(1024) unsigned char g_xb[(size_t)BDIM * NIN]; // sign(x) as e4m3
__device__ __align__(1024) unsigned char g_wb[(size_t)NOUT * NIN]; // sign(fp-mean) as e4m3
__device__ float g_scale[NOUT];

// ==================== PTX helpers (baseline PTX only) ====================
__device__ __forceinline__ uint32_t smem_to_u32(const void* p) {
    uint32_t a;
    asm("{ .reg .u64 t; cvta.to.shared.u64 t, %1; cvt.u32.u64 %0, t; }" : "=r"(a) : "l"(p));
    return a;
}

#define MBARRIER_INIT(addr, cnt) \
    asm volatile("mbarrier.init.shared.b64 [%0], %1;" :: "r"((uint32_t)(addr)), "r"((uint32_t)(cnt)) : "memory")

#define MBARRIER_ARRIVE(addr) \
    asm volatile("mbarrier.arrive.shared.b64 _, [%0];" :: "r"((uint32_t)(addr)) : "memory")

#define MBARRIER_EXPECT_TX(addr, bytes) \
    asm volatile("mbarrier.arrive.expect_tx.shared.b64 _, [%0], %1;" :: "r"((uint32_t)(addr)), "r"((uint32_t)(bytes)) : "memory")

#define MBARRIER_WAIT_PARITY(mbar_smem_addr, phase_parity) do { \
    uint32_t _mbar = (uint32_t)(mbar_smem_addr); \
    uint32_t _parity = (uint32_t)(phase_parity); \
    uint32_t _done; \
    asm volatile( \
        "{\n\t.reg .pred p;\n\t" \
        "mbarrier.try_wait.parity.acquire.cta.shared::cta.b64 p, [%1], %2;\n\t" \
        "selp.b32 %0, 1, 0, p;\n\t}" \
        : "=r"(_done) : "r"(_mbar), "r"(_parity) : "memory"); \
    if (!_done) { \
        asm volatile( \
            "{\n\t.reg .pred P1;\n\t" \
            "WAIT_LOOP_%=:\n\t" \
            "mbarrier.try_wait.parity.acquire.cta.shared::cta.b64 P1, [%0], %1, 0x989680;\n\t" \
            "@P1 bra.uni WAIT_DONE_%=;\n\t" \
            "bra.uni WAIT_LOOP_%=;\n\t" \
            "WAIT_DONE_%=:\n\t}" \
            :: "r"(_mbar), "r"(_parity) : "memory"); \
    } \
} while (0)

#define TMA_LOAD_3D(smem_addr, tensor_map, cx, cy, cz, mbar) \
    asm volatile( \
        "cp.async.bulk.tensor.3d.shared::cta.global.tile.mbarrier::complete_tx::bytes " \
        "[%0], [%1, {%2, %3, %4}], [%5];" \
        :: "r"((uint32_t)(smem_addr)), "l"(tensor_map), "r"((int32_t)(cx)), "r"((int32_t)(cy)), \
           "r"((int32_t)(cz)), "r"((uint32_t)(mbar)) : "memory")

#define FENCE_PROXY_ASYNC_SHARED_CTA() asm volatile("fence.proxy.async.shared::cta;" ::: "memory")

#define LDMATRIX_X4(r0, r1, r2, r3, addr) \
    asm volatile("ldmatrix.sync.aligned.m8n8.x4.shared.b16 {%0,%1,%2,%3}, [%4];" \
                 : "=r"(r0), "=r"(r1), "=r"(r2), "=r"(r3) : "r"(addr))

// legacy FP8 QMMA with F16 accumulator: m16n8k32, e4m3 x e4m3 (sm_89+ baseline).
#define MMA_F8_H(d, a, b) \
    asm volatile("mma.sync.aligned.m16n8k32.row.col.f16.e4m3.e4m3.f16 " \
                 "{%0,%1}, {%2,%3,%4,%5}, {%6,%7}, {%0,%1};" \
                 : "+r"((d)[0]), "+r"((d)[1]) \
                 : "r"((a)[0]), "r"((a)[1]), "r"((a)[2]), "r"((a)[3]), \
                   "r"((b)[0]), "r"((b)[1]))

// ==================== merged prep kernel ====================
// e4m3: +1.0 = 0x38, -1.0 = 0xB8, 0.0 = 0x00
__device__ __forceinline__ uint32_t sgn8(float v) {
    return v > 0.f ? 0x38u : (v < 0.f ? 0xB8u : 0x00u);
}

__device__ __forceinline__ float4 ldcs4(const float4* p) {
    float4 v;
    asm volatile("ld.global.cs.v4.f32 {%0,%1,%2,%3}, [%4];"
                 : "=f"(v.x), "=f"(v.y), "=f"(v.z), "=f"(v.w) : "l"(p));
    return v;
}

// blocks [0, NOUT): one weight row each (center, clamp, sign, scale).
// blocks [NOUT, NOUT+XBLOCKS): 4096-byte x chunks (sign pack).
// Inputs are read ONCE -> streaming loads (evict-first) keep L2 free for the
// freshly-written xb/wb that the GEMM's TMA consumes right after.
__global__ void __launch_bounds__(256) prep_all_kernel(const float4* __restrict__ x,
                                                       uint4* __restrict__ xb,
                                                       const float* __restrict__ w,
                                                       uint4* __restrict__ wb,
                                                       float* __restrict__ scale) {
    const int tid = threadIdx.x;
    if (blockIdx.x >= NOUT) {
        // ---- x path ----
        const size_t i = (size_t)(blockIdx.x - NOUT) * 256 + tid;
        uint32_t p[4];
#pragma unroll
        for (int q = 0; q < 4; q++) {
            float4 v = ldcs4(x + i * 4 + q);
            p[q] = sgn8(v.x) | (sgn8(v.y) << 8) | (sgn8(v.z) << 16) | (sgn8(v.w) << 24);
        }
        xb[i] = make_uint4(p[0], p[1], p[2], p[3]);
        return;
    }

    // ---- w path ----
    __shared__ float red[256];
    const int row = blockIdx.x;
    const float4* wr = (const float4*)(w + (size_t)row * NIN);

    float4 v[4];
    float s = 0.f;
#pragma unroll
    for (int q = 0; q < 4; q++) {
        v[q] = ldcs4(wr + tid * 4 + q);
        s += (v[q].x + v[q].y) + (v[q].z + v[q].w);
    }
    red[tid] = s;
    __syncthreads();
    for (int o = 128; o > 0; o >>= 1) {
        if (tid < o) red[tid] += red[tid + o];
        __syncthreads();
    }
    const float mean = red[0] * (1.f / NIN);
    __syncthreads();

    float a = 0.f;
    uint32_t p[4];
#pragma unroll
    for (int q = 0; q < 4; q++) {
        float f0 = v[q].x - mean, f1 = v[q].y - mean, f2 = v[q].z - mean, f3 = v[q].w - mean;
        a += fabsf(fminf(fmaxf(f0, -1.f), 1.f));
        a += fabsf(fminf(fmaxf(f1, -1.f), 1.f));
        a += fabsf(fminf(fmaxf(f2, -1.f), 1.f));
        a += fabsf(fminf(fmaxf(f3, -1.f), 1.f));
        p[q] = sgn8(f0) | (sgn8(f1) << 8) | (sgn8(f2) << 16) | (sgn8(f3) << 24);
    }
    wb[(size_t)row * (NIN / 16) + tid] = make_uint4(p[0], p[1], p[2], p[3]);

    red[tid] = a;
    __syncthreads();
    for (int o = 128; o > 0; o >>= 1) {
        if (tid < o) red[tid] += red[tid + o];
        __syncthreads();
    }
    if (tid == 0) scale[row] = red[0] * (1.f / NIN);
}

// ==================== GEMM kernel (legacy FP8 QMMA f16-acc, warp-specialized) ====================
// 288 threads: warps 0-7 math (2m x 4n grid, 64x32 warp tile), warp 8 = TMA producer.
// 2 CTAs/SM, N-fast rasterization. This exact configuration is the measured optimum
// (R10/R13: 1232.8-1233.7us); all mainloop/structural perturbations (R11, R12, R14)
// regressed — the loop body must stay byte-identical.
__global__ void __launch_bounds__(NTHREADS, 2)
xnor_gemm_kernel(const __grid_constant__ CUtensorMap tma_a,
                 const __grid_constant__ CUtensorMap tma_b,
                 const float* __restrict__ scale,
                 const float* __restrict__ bias,
                 float* __restrict__ out) {
    extern __shared__ char smem[];
    const uint32_t sb = smem_to_u32(smem);
    const int tid = threadIdx.x;
    const int wid = tid >> 5;
    const int lane = tid & 31;

    const int n0 = blockIdx.x * BN;   // N fastest
    const int m0 = blockIdx.y * BM;

    if (tid == 0) {
#pragma unroll
        for (int s = 0; s < STAGES; s++) {
            MBARRIER_INIT(sb + SM_BARS + 8u * s, 1);                    // full (TMA tx)
            MBARRIER_INIT(sb + SM_BARS + 8u * (STAGES + s), MATH_WARPS); // empty
        }
        FENCE_PROXY_ASYNC_SHARED_CTA();
    }
    // stage scale/bias for this n-tile
    {
        float* s_sc = (float*)(smem + SM_SC);
        float* s_bi = (float*)(smem + SM_BI);
        if (tid < BN) {
            s_sc[tid] = scale[n0 + tid];
            s_bi[tid] = bias[n0 + tid];
        }
    }
    __syncthreads();  // barriers initialized + scale/bias visible

    if (wid == MATH_WARPS) {
        // ================= producer warp =================
        if (lane == 0) {
#pragma unroll
            for (int p = 0; p < STAGES; p++) {
                MBARRIER_EXPECT_TX(sb + SM_BARS + 8u * p, STAGE_BYTES);
                const uint32_t st = sb + SM_TILE0 + (uint32_t)p * STAGE_BYTES;
                TMA_LOAD_3D(st, &tma_a, p * BK, m0, 0, sb + SM_BARS + 8u * p);
                TMA_LOAD_3D(st + A_BYTES, &tma_b, p * BK, n0, 0, sb + SM_BARS + 8u * p);
            }
            int s = 0, eph = 0;
            for (int ld = STAGES; ld < KITERS; ++ld) {
                MBARRIER_WAIT_PARITY(sb + SM_BARS + 8u * (STAGES + s), eph);
                MBARRIER_EXPECT_TX(sb + SM_BARS + 8u * s, STAGE_BYTES);
                const uint32_t st = sb + SM_TILE0 + (uint32_t)s * STAGE_BYTES;
                TMA_LOAD_3D(st, &tma_a, ld * BK, m0, 0, sb + SM_BARS + 8u * s);
                TMA_LOAD_3D(st + A_BYTES, &tma_b, ld * BK, n0, 0, sb + SM_BARS + 8u * s);
                if (++s == STAGES) { s = 0; eph ^= 1; }
            }
        }
        return;
    }

    // ================= math warps =================
    const int warp_m = wid & 1;   // 0..1  (64 rows each)
    const int warp_n = wid >> 1;  // 0..3  (32 cols each)
    const int rlo = lane & 7;
    const int sub = (lane >> 3) & 3;

    // precomputed ldmatrix offsets (SW128: phys = row*128 + (kbyte ^ ((row&7)<<4)))
    uint32_t aRow[4], bRow[2], kx[4];
#pragma unroll
    for (int im = 0; im < 4; im++)
        aRow[im] = (uint32_t)(warp_m * 64 + im * 16 + (sub & 1) * 8 + rlo) * 128u;
#pragma unroll
    for (int bp = 0; bp < 2; bp++)
        bRow[bp] = (uint32_t)(warp_n * 32 + bp * 16 + (sub & 1) * 8 + rlo) * 128u;
#pragma unroll
    for (int ks = 0; ks < 4; ks++)
        kx[ks] = (uint32_t)((ks * 32 + ((sub >> 1) & 1) * 16) ^ (rlo << 4));

    // f16x2 accumulators (exact: |partial sums| << 2048)
    uint32_t d[4][4][2];
#pragma unroll
    for (int im = 0; im < 4; im++)
#pragma unroll
        for (int in = 0; in < 4; in++) { d[im][in][0] = 0u; d[im][in][1] = 0u; }

    int s = 0, ph = 0;
    for (int it = 0; it < KITERS; ++it) {
        MBARRIER_WAIT_PARITY(sb + SM_BARS + 8u * s, ph);
        const uint32_t saA = sb + SM_TILE0 + (uint32_t)s * STAGE_BYTES;
        const uint32_t saB = saA + A_BYTES;

#pragma unroll
        for (int ks = 0; ks < 4; ks++) {
            uint32_t a[4][4];
            uint32_t b[4][2];
#pragma unroll
            for (int im = 0; im < 4; im++) {
                LDMATRIX_X4(a[im][0], a[im][1], a[im][2], a[im][3], saA + aRow[im] + kx[ks]);
            }
#pragma unroll
            for (int bp = 0; bp < 2; bp++) {
                uint32_t r0, r1, r2, r3;
                LDMATRIX_X4(r0, r1, r2, r3, saB + bRow[bp] + kx[ks]);
                b[2 * bp][0] = r0; b[2 * bp + 1][0] = r1;
                b[2 * bp][1] = r2; b[2 * bp + 1][1] = r3;
            }
#pragma unroll
            for (int im = 0; im < 4; im++)
#pragma unroll
                for (int in = 0; in < 4; in++) MMA_F8_H(d[im][in], a[im], b[in]);
        }

        if (lane == 0) MBARRIER_ARRIVE(sb + SM_BARS + 8u * (STAGES + s));
        if (++s == STAGES) { s = 0; ph ^= 1; }
    }

    // -------- epilogue: out = float(acc) * scale[n] + bias[n] --------
    const float* s_sc = (const float*)(smem + SM_SC);
    const float* s_bi = (const float*)(smem + SM_BI);
    const int gm0 = m0 + warp_m * 64 + (lane >> 2);
    const int lc0 = warp_n * 32 + (lane & 3) * 2;

#pragma unroll
    for (int im = 0; im < 4; im++) {
#pragma unroll
        for (int in = 0; in < 4; in++) {
            const int lc = lc0 + in * 8;
            const float sc0 = s_sc[lc], sc1 = s_sc[lc + 1];
            const float bi0 = s_bi[lc], bi1 = s_bi[lc + 1];
            const int row0 = gm0 + im * 16;
            const float2 lo = __half22float2(*reinterpret_cast<const __half2*>(&d[im][in][0]));
            const float2 hi = __half22float2(*reinterpret_cast<const __half2*>(&d[im][in][1]));
            float2 v0, v1;
            v0.x = lo.x * sc0 + bi0;
            v0.y = lo.y * sc1 + bi1;
            v1.x = hi.x * sc0 + bi0;
            v1.y = hi.y * sc1 + bi1;
            *reinterpret_cast<float2*>(out + (size_t)row0 * NOUT + n0 + lc) = v0;
            *reinterpret_cast<float2*>(out + (size_t)(row0 + 8) * NOUT + n0 + lc) = v1;
        }
    }
}

// ==================== host launch ====================
typedef CUresult (*TMEncodeFn)(CUtensorMap*, CUtensorMapDataType, cuuint32_t, void*,
                               const cuuint64_t*, const cuuint64_t*, const cuuint32_t*,
                               const cuuint32_t*, CUtensorMapInterleave, CUtensorMapSwizzle,
                               CUtensorMapL2promotion, CUtensorMapFloatOOBfill);

extern "C" void kernel_launch(void* const* d_in, const int* in_sizes, int n_in,
                              void* d_out, int out_size) {
    const float* x    = (const float*)d_in[0];
    const float* fp   = (const float*)d_in[1];
    const float* bias = (const float*)d_in[2];
    float* out = (float*)d_out;

    void *xb = nullptr, *wb = nullptr, *scale = nullptr;
    cudaGetSymbolAddress(&xb, g_xb);
    cudaGetSymbolAddress(&wb, g_wb);
    cudaGetSymbolAddress(&scale, g_scale);

    // merged preprocessing: w-rows (blocks 0..4095) + x-chunks (blocks 4096..20479)
    prep_all_kernel<<<NOUT + XBLOCKS, 256>>>((const float4*)x, (uint4*)xb,
                                             fp, (uint4*)wb, (float*)scale);

    // TMA descriptors (driver entry point via runtime — no -lcuda needed)
    TMEncodeFn enc = nullptr;
    cudaDriverEntryPointQueryResult qr;
    cudaGetDriverEntryPoint("cuTensorMapEncodeTiled", (void**)&enc, cudaEnableDefault, &qr);

    CUtensorMap ta, tb;
    cuuint32_t es[3] = {1, 1, 1};
    {
        cuuint64_t dims[3] = {NIN, BDIM, 1};
        cuuint64_t str[2]  = {NIN, (cuuint64_t)NIN * BDIM};
        cuuint32_t box[3]  = {BK, BM, 1};
        enc(&ta, CU_TENSOR_MAP_DATA_TYPE_UINT8, 3, xb, dims, str, box, es,
            CU_TENSOR_MAP_INTERLEAVE_NONE, CU_TENSOR_MAP_SWIZZLE_128B,
            CU_TENSOR_MAP_L2_PROMOTION_L2_128B, CU_TENSOR_MAP_FLOAT_OOB_FILL_NONE);
    }
    {
        cuuint64_t dims[3] = {NIN, NOUT, 1};
        cuuint64_t str[2]  = {NIN, (cuuint64_t)NIN * NOUT};
        cuuint32_t box[3]  = {BK, BN, 1};
        enc(&tb, CU_TENSOR_MAP_DATA_TYPE_UINT8, 3, wb, dims, str, box, es,
            CU_TENSOR_MAP_INTERLEAVE_NONE, CU_TENSOR_MAP_SWIZZLE_128B,
            CU_TENSOR_MAP_L2_PROMOTION_L2_128B, CU_TENSOR_MAP_FLOAT_OOB_FILL_NONE);
    }

    cudaFuncSetAttribute(xnor_gemm_kernel, cudaFuncAttributeMaxDynamicSharedMemorySize,
                         SMEM_TOTAL);
    // grid: x = N-tiles (fast-varying), y = M-tiles
    xnor_gemm_kernel<<<dim3(NOUT / BN, BDIM / BM, 1), NTHREADS, SMEM_TOTAL>>>(
        ta, tb, (const float*)scale, bias, out);
}

// round 16
// speedup vs baseline: 1.0215x; 1.0016x over previous
#include <cuda_runtime.h>
#include <cuda.h>
#include <cuda_fp16.h>
#include <cstdint>

// ==================== problem constants ====================
static constexpr int BDIM = 16384;
static constexpr int NIN  = 4096;
static constexpr int NOUT = 4096;

// ==================== GEMM tiling ====================
static constexpr int BM = 128;
static constexpr int BN = 128;
static constexpr int BK = 128;            // fp8 elements of K per stage
static constexpr int STAGES = 3;
static constexpr int KITERS = NIN / BK;   // 32

// smem layout (dynamic)
static constexpr unsigned SM_BARS  = 0;   // full[s] at 8s; empty[s] at 8*(STAGES+s)
static constexpr unsigned SM_SC    = 128;                   // BN floats (scale)
static constexpr unsigned SM_BI    = SM_SC + BN * 4;
static constexpr unsigned SM_TILE0 = 4096;                  // 1024-aligned tiles
static constexpr unsigned A_BYTES     = BM * BK;            // 16384
static constexpr unsigned B_BYTES     = BN * BK;            // 16384
static constexpr unsigned STAGE_BYTES = A_BYTES + B_BYTES;  // 32768
static constexpr unsigned SMEM_TOTAL  = SM_TILE0 + STAGES * STAGE_BYTES; // 102400 (2 CTAs/SM)

static constexpr int MATH_WARPS = 8;
static constexpr int NTHREADS   = (MATH_WARPS + 1) * 32;    // 288: 8 math + 1 producer

// merged prep grid: blocks [0, NOUT) do weight rows; [NOUT, NOUT + XBLOCKS) do x chunks
static constexpr int XBLOCKS = BDIM * NIN / 16 / 256;       // 16384

// ==================== scratch (device globals: no allocs allowed) ====================
__device__ __align__(1024) unsigned char g_xb[(size_t)BDIM * NIN]; // sign(x) as e4m3
__device__ __align__(1024) unsigned char g_wb[(size_t)NOUT * NIN]; // sign(fp-mean) as e4m3
__device__ float g_scale[NOUT];

// ==================== PTX helpers (baseline PTX only) ====================
__device__ __forceinline__ uint32_t smem_to_u32(const void* p) {
    uint32_t a;
    asm("{ .reg .u64 t; cvta.to.shared.u64 t, %1; cvt.u32.u64 %0, t; }" : "=r"(a) : "l"(p));
    return a;
}

#define MBARRIER_INIT(addr, cnt) \
    asm volatile("mbarrier.init.shared.b64 [%0], %1;" :: "r"((uint32_t)(addr)), "r"((uint32_t)(cnt)) : "memory")

#define MBARRIER_ARRIVE(addr) \
    asm volatile("mbarrier.arrive.shared.b64 _, [%0];" :: "r"((uint32_t)(addr)) : "memory")

#define MBARRIER_EXPECT_TX(addr, bytes) \
    asm volatile("mbarrier.arrive.expect_tx.shared.b64 _, [%0], %1;" :: "r"((uint32_t)(addr)), "r"((uint32_t)(bytes)) : "memory")

#define MBARRIER_WAIT_PARITY(mbar_smem_addr, phase_parity) do { \
    uint32_t _mbar = (uint32_t)(mbar_smem_addr); \
    uint32_t _parity = (uint32_t)(phase_parity); \
    uint32_t _done; \
    asm volatile( \
        "{\n\t.reg .pred p;\n\t" \
        "mbarrier.try_wait.parity.acquire.cta.shared::cta.b64 p, [%1], %2;\n\t" \
        "selp.b32 %0, 1, 0, p;\n\t}" \
        : "=r"(_done) : "r"(_mbar), "r"(_parity) : "memory"); \
    if (!_done) { \
        asm volatile( \
            "{\n\t.reg .pred P1;\n\t" \
            "WAIT_LOOP_%=:\n\t" \
            "mbarrier.try_wait.parity.acquire.cta.shared::cta.b64 P1, [%0], %1, 0x989680;\n\t" \
            "@P1 bra.uni WAIT_DONE_%=;\n\t" \
            "bra.uni WAIT_LOOP_%=;\n\t" \
            "WAIT_DONE_%=:\n\t}" \
            :: "r"(_mbar), "r"(_parity) : "memory"); \
    } \
} while (0)

// Relaxed variant: producer-only. Safe because all post-wait smem accesses by
// the producer are async-proxy (TMA), which carry their own ordering.
#define MBARRIER_WAIT_PARITY_RELAXED(mbar_smem_addr, phase_parity) do { \
    uint32_t _mbar = (uint32_t)(mbar_smem_addr); \
    uint32_t _parity = (uint32_t)(phase_parity); \
    uint32_t _done; \
    asm volatile( \
        "{\n\t.reg .pred p;\n\t" \
        "mbarrier.try_wait.parity.relaxed.cta.shared::cta.b64 p, [%1], %2, 0x989680;\n\t" \
        "selp.b32 %0, 1, 0, p;\n\t}" \
        : "=r"(_done) : "r"(_mbar), "r"(_parity) : "memory"); \
    if (!_done) { \
        asm volatile( \
            "{\n\t.reg .pred P1;\n\t" \
            "WAIT_LOOP_%=:\n\t" \
            "mbarrier.try_wait.parity.relaxed.cta.shared::cta.b64 P1, [%0], %1, 0x989680;\n\t" \
            "@P1 bra.uni WAIT_DONE_%=;\n\t" \
            "bra.uni WAIT_LOOP_%=;\n\t" \
            "WAIT_DONE_%=:\n\t}" \
            :: "r"(_mbar), "r"(_parity) : "memory"); \
    } \
} while (0)

#define TMA_LOAD_3D(smem_addr, tensor_map, cx, cy, cz, mbar) \
    asm volatile( \
        "cp.async.bulk.tensor.3d.shared::cta.global.tile.mbarrier::complete_tx::bytes " \
        "[%0], [%1, {%2, %3, %4}], [%5];" \
        :: "r"((uint32_t)(smem_addr)), "l"(tensor_map), "r"((int32_t)(cx)), "r"((int32_t)(cy)), \
           "r"((int32_t)(cz)), "r"((uint32_t)(mbar)) : "memory")

#define FENCE_PROXY_ASYNC_SHARED_CTA() asm volatile("fence.proxy.async.shared::cta;" ::: "memory")

#define LDMATRIX_X4(r0, r1, r2, r3, addr) \
    asm volatile("ldmatrix.sync.aligned.m8n8.x4.shared.b16 {%0,%1,%2,%3}, [%4];" \
                 : "=r"(r0), "=r"(r1), "=r"(r2), "=r"(r3) : "r"(addr))

// legacy FP8 QMMA with F16 accumulator: m16n8k32, e4m3 x e4m3 (sm_89+ baseline).
#define MMA_F8_H(d, a, b) \
    asm volatile("mma.sync.aligned.m16n8k32.row.col.f16.e4m3.e4m3.f16 " \
                 "{%0,%1}, {%2,%3,%4,%5}, {%6,%7}, {%0,%1};" \
                 : "+r"((d)[0]), "+r"((d)[1]) \
                 : "r"((a)[0]), "r"((a)[1]), "r"((a)[2]), "r"((a)[3]), \
                   "r"((b)[0]), "r"((b)[1]))

// ==================== merged prep kernel ====================
// e4m3: +1.0 = 0x38, -1.0 = 0xB8, 0.0 = 0x00
__device__ __forceinline__ uint32_t sgn8(float v) {
    return v > 0.f ? 0x38u : (v < 0.f ? 0xB8u : 0x00u);
}

__device__ __forceinline__ float4 ldcs4(const float4* p) {
    float4 v;
    asm volatile("ld.global.cs.v4.f32 {%0,%1,%2,%3}, [%4];"
                 : "=f"(v.x), "=f"(v.y), "=f"(v.z), "=f"(v.w) : "l"(p));
    return v;
}

// blocks [0, NOUT): one weight row each (center, clamp, sign, scale).
// blocks [NOUT, NOUT+XBLOCKS): 4096-byte x chunks (sign pack).
__global__ void __launch_bounds__(256) prep_all_kernel(const float4* __restrict__ x,
                                                       uint4* __restrict__ xb,
                                                       const float* __restrict__ w,
                                                       uint4* __restrict__ wb,
                                                       float* __restrict__ scale) {
    const int tid = threadIdx.x;
    if (blockIdx.x >= NOUT) {
        // ---- x path ----
        const size_t i = (size_t)(blockIdx.x - NOUT) * 256 + tid;
        uint32_t p[4];
#pragma unroll
        for (int q = 0; q < 4; q++) {
            float4 v = ldcs4(x + i * 4 + q);
            p[q] = sgn8(v.x) | (sgn8(v.y) << 8) | (sgn8(v.z) << 16) | (sgn8(v.w) << 24);
        }
        xb[i] = make_uint4(p[0], p[1], p[2], p[3]);
        return;
    }

    // ---- w path ----
    __shared__ float red[256];
    const int row = blockIdx.x;
    const float4* wr = (const float4*)(w + (size_t)row * NIN);

    float4 v[4];
    float s = 0.f;
#pragma unroll
    for (int q = 0; q < 4; q++) {
        v[q] = ldcs4(wr + tid * 4 + q);
        s += (v[q].x + v[q].y) + (v[q].z + v[q].w);
    }
    red[tid] = s;
    __syncthreads();
    for (int o = 128; o > 0; o >>= 1) {
        if (tid < o) red[tid] += red[tid + o];
        __syncthreads();
    }
    const float mean = red[0] * (1.f / NIN);
    __syncthreads();

    float a = 0.f;
    uint32_t p[4];
#pragma unroll
    for (int q = 0; q < 4; q++) {
        float f0 = v[q].x - mean, f1 = v[q].y - mean, f2 = v[q].z - mean, f3 = v[q].w - mean;
        a += fabsf(fminf(fmaxf(f0, -1.f), 1.f));
        a += fabsf(fminf(fmaxf(f1, -1.f), 1.f));
        a += fabsf(fminf(fmaxf(f2, -1.f), 1.f));
        a += fabsf(fminf(fmaxf(f3, -1.f), 1.f));
        p[q] = sgn8(f0) | (sgn8(f1) << 8) | (sgn8(f2) << 16) | (sgn8(f3) << 24);
    }
    wb[(size_t)row * (NIN / 16) + tid] = make_uint4(p[0], p[1], p[2], p[3]);

    red[tid] = a;
    __syncthreads();
    for (int o = 128; o > 0; o >>= 1) {
        if (tid < o) red[tid] += red[tid + o];
        __syncthreads();
    }
    if (tid == 0) scale[row] = red[0] * (1.f / NIN);
}

// ==================== GEMM kernel (legacy FP8 QMMA f16-acc, warp-specialized) ====================
// 288 threads: warps 0-7 math (2m x 4n grid, 64x32 warp tile), warp 8 = TMA producer.
// 2 CTAs/SM, N-fast rasterization. Math mainloop byte-identical to the measured
// optimum (R10/R13: 1232.8us); producer uses relaxed empty-waits (TMA-only after).
__global__ void __launch_bounds__(NTHREADS, 2)
xnor_gemm_kernel(const __grid_constant__ CUtensorMap tma_a,
                 const __grid_constant__ CUtensorMap tma_b,
                 const float* __restrict__ scale,
                 const float* __restrict__ bias,
                 float* __restrict__ out) {
    extern __shared__ char smem[];
    const uint32_t sb = smem_to_u32(smem);
    const int tid = threadIdx.x;
    const int wid = tid >> 5;
    const int lane = tid & 31;

    const int n0 = blockIdx.x * BN;   // N fastest
    const int m0 = blockIdx.y * BM;

    if (tid == 0) {
#pragma unroll
        for (int s = 0; s < STAGES; s++) {
            MBARRIER_INIT(sb + SM_BARS + 8u * s, 1);                    // full (TMA tx)
            MBARRIER_INIT(sb + SM_BARS + 8u * (STAGES + s), MATH_WARPS); // empty
        }
        FENCE_PROXY_ASYNC_SHARED_CTA();
    }
    // stage scale/bias for this n-tile
    {
        float* s_sc = (float*)(smem + SM_SC);
        float* s_bi = (float*)(smem + SM_BI);
        if (tid < BN) {
            s_sc[tid] = scale[n0 + tid];
            s_bi[tid] = bias[n0 + tid];
        }
    }
    __syncthreads();  // barriers initialized + scale/bias visible

    if (wid == MATH_WARPS) {
        // ================= producer warp =================
        if (lane == 0) {
#pragma unroll
            for (int p = 0; p < STAGES; p++) {
                MBARRIER_EXPECT_TX(sb + SM_BARS + 8u * p, STAGE_BYTES);
                const uint32_t st = sb + SM_TILE0 + (uint32_t)p * STAGE_BYTES;
                TMA_LOAD_3D(st, &tma_a, p * BK, m0, 0, sb + SM_BARS + 8u * p);
                TMA_LOAD_3D(st + A_BYTES, &tma_b, p * BK, n0, 0, sb + SM_BARS + 8u * p);
            }
            int s = 0, eph = 0;
            for (int ld = STAGES; ld < KITERS; ++ld) {
                MBARRIER_WAIT_PARITY_RELAXED(sb + SM_BARS + 8u * (STAGES + s), eph);
                MBARRIER_EXPECT_TX(sb + SM_BARS + 8u * s, STAGE_BYTES);
                const uint32_t st = sb + SM_TILE0 + (uint32_t)s * STAGE_BYTES;
                TMA_LOAD_3D(st, &tma_a, ld * BK, m0, 0, sb + SM_BARS + 8u * s);
                TMA_LOAD_3D(st + A_BYTES, &tma_b, ld * BK, n0, 0, sb + SM_BARS + 8u * s);
                if (++s == STAGES) { s = 0; eph ^= 1; }
            }
        }
        return;
    }

    // ================= math warps =================
    const int warp_m = wid & 1;   // 0..1  (64 rows each)
    const int warp_n = wid >> 1;  // 0..3  (32 cols each)
    const int rlo = lane & 7;
    const int sub = (lane >> 3) & 3;

    // precomputed ldmatrix offsets (SW128: phys = row*128 + (kbyte ^ ((row&7)<<4)))
    uint32_t aRow[4], bRow[2], kx[4];
#pragma unroll
    for (int im = 0; im < 4; im++)
        aRow[im] = (uint32_t)(warp_m * 64 + im * 16 + (sub & 1) * 8 + rlo) * 128u;
#pragma unroll
    for (int bp = 0; bp < 2; bp++)
        bRow[bp] = (uint32_t)(warp_n * 32 + bp * 16 + (sub & 1) * 8 + rlo) * 128u;
#pragma unroll
    for (int ks = 0; ks < 4; ks++)
        kx[ks] = (uint32_t)((ks * 32 + ((sub >> 1) & 1) * 16) ^ (rlo << 4));

    // f16x2 accumulators (exact: |partial sums| << 2048)
    uint32_t d[4][4][2];
#pragma unroll
    for (int im = 0; im < 4; im++)
#pragma unroll
        for (int in = 0; in < 4; in++) { d[im][in][0] = 0u; d[im][in][1] = 0u; }

    int s = 0, ph = 0;
    for (int it = 0; it < KITERS; ++it) {
        MBARRIER_WAIT_PARITY(sb + SM_BARS + 8u * s, ph);
        const uint32_t saA = sb + SM_TILE0 + (uint32_t)s * STAGE_BYTES;
        const uint32_t saB = saA + A_BYTES;

#pragma unroll
        for (int ks = 0; ks < 4; ks++) {
            uint32_t a[4][4];
            uint32_t b[4][2];
#pragma unroll
            for (int im = 0; im < 4; im++) {
                LDMATRIX_X4(a[im][0], a[im][1], a[im][2], a[im][3], saA + aRow[im] + kx[ks]);
            }
#pragma unroll
            for (int bp = 0; bp < 2; bp++) {
                uint32_t r0, r1, r2, r3;
                LDMATRIX_X4(r0, r1, r2, r3, saB + bRow[bp] + kx[ks]);
                b[2 * bp][0] = r0; b[2 * bp + 1][0] = r1;
                b[2 * bp][1] = r2; b[2 * bp + 1][1] = r3;
            }
#pragma unroll
            for (int im = 0; im < 4; im++)
#pragma unroll
                for (int in = 0; in < 4; in++) MMA_F8_H(d[im][in], a[im], b[in]);
        }

        if (lane == 0) MBARRIER_ARRIVE(sb + SM_BARS + 8u * (STAGES + s));
        if (++s == STAGES) { s = 0; ph ^= 1; }
    }

    // -------- epilogue: out = float(acc) * scale[n] + bias[n] --------
    const float* s_sc = (const float*)(smem + SM_SC);
    const float* s_bi = (const float*)(smem + SM_BI);
    const int gm0 = m0 + warp_m * 64 + (lane >> 2);
    const int lc0 = warp_n * 32 + (lane & 3) * 2;

#pragma unroll
    for (int im = 0; im < 4; im++) {
#pragma unroll
        for (int in = 0; in < 4; in++) {
            const int lc = lc0 + in * 8;
            const float sc0 = s_sc[lc], sc1 = s_sc[lc + 1];
            const float bi0 = s_bi[lc], bi1 = s_bi[lc + 1];
            const int row0 = gm0 + im * 16;
            const float2 lo = __half22float2(*reinterpret_cast<const __half2*>(&d[im][in][0]));
            const float2 hi = __half22float2(*reinterpret_cast<const __half2*>(&d[im][in][1]));
            float2 v0, v1;
            v0.x = lo.x * sc0 + bi0;
            v0.y = lo.y * sc1 + bi1;
            v1.x = hi.x * sc0 + bi0;
            v1.y = hi.y * sc1 + bi1;
            *reinterpret_cast<float2*>(out + (size_t)row0 * NOUT + n0 + lc) = v0;
            *reinterpret_cast<float2*>(out + (size_t)(row0 + 8) * NOUT + n0 + lc) = v1;
        }
    }
}

// ==================== host launch ====================
typedef CUresult (*TMEncodeFn)(CUtensorMap*, CUtensorMapDataType, cuuint32_t, void*,
                               const cuuint64_t*, const cuuint64_t*, const cuuint32_t*,
                               const cuuint32_t*, CUtensorMapInterleave, CUtensorMapSwizzle,
                               CUtensorMapL2promotion, CUtensorMapFloatOOBfill);

extern "C" void kernel_launch(void* const* d_in, const int* in_sizes, int n_in,
                              void* d_out, int out_size) {
    const float* x    = (const float*)d_in[0];
    const float* fp   = (const float*)d_in[1];
    const float* bias = (const float*)d_in[2];
    float* out = (float*)d_out;

    void *xb = nullptr, *wb = nullptr, *scale = nullptr;
    cudaGetSymbolAddress(&xb, g_xb);
    cudaGetSymbolAddress(&wb, g_wb);
    cudaGetSymbolAddress(&scale, g_scale);

    // merged preprocessing: w-rows (blocks 0..4095) + x-chunks (blocks 4096..20479)
    prep_all_kernel<<<NOUT + XBLOCKS, 256>>>((const float4*)x, (uint4*)xb,
                                             fp, (uint4*)wb, (float*)scale);

    // TMA descriptors (driver entry point via runtime — no -lcuda needed)
    TMEncodeFn enc = nullptr;
    cudaDriverEntryPointQueryResult qr;
    cudaGetDriverEntryPoint("cuTensorMapEncodeTiled", (void**)&enc, cudaEnableDefault, &qr);

    CUtensorMap ta, tb;
    cuuint32_t es[3] = {1, 1, 1};
    {
        cuuint64_t dims[3] = {NIN, BDIM, 1};
        cuuint64_t str[2]  = {NIN, (cuuint64_t)NIN * BDIM};
        cuuint32_t box[3]  = {BK, BM, 1};
        enc(&ta, CU_TENSOR_MAP_DATA_TYPE_UINT8, 3, xb, dims, str, box, es,
            CU_TENSOR_MAP_INTERLEAVE_NONE, CU_TENSOR_MAP_SWIZZLE_128B,
            CU_TENSOR_MAP_L2_PROMOTION_L2_128B, CU_TENSOR_MAP_FLOAT_OOB_FILL_NONE);
    }
    {
        cuuint64_t dims[3] = {NIN, NOUT, 1};
        cuuint64_t str[2]  = {NIN, (cuuint64_t)NIN * NOUT};
        cuuint32_t box[3]  = {BK, BN, 1};
        enc(&tb, CU_TENSOR_MAP_DATA_TYPE_UINT8, 3, wb, dims, str, box, es,
            CU_TENSOR_MAP_INTERLEAVE_NONE, CU_TENSOR_MAP_SWIZZLE_128B,
            CU_TENSOR_MAP_L2_PROMOTION_L2_128B, CU_TENSOR_MAP_FLOAT_OOB_FILL_NONE);
    }

    cudaFuncSetAttribute(xnor_gemm_kernel, cudaFuncAttributeMaxDynamicSharedMemorySize,
                         SMEM_TOTAL);
    // grid: x = N-tiles (fast-varying), y = M-tiles
    xnor_gemm_kernel<<<dim3(NOUT / BN, BDIM / BM, 1), NTHREADS, SMEM_TOTAL>>>(
        ta, tb, (const float*)scale, bias, out);
}

// round 17
// speedup vs baseline: 1.0223x; 1.0008x over previous
#include <cuda_runtime.h>
#include <cuda.h>
#include <cuda_fp16.h>
#include <cstdint>

// ==================== problem constants ====================
static constexpr int BDIM = 16384;
static constexpr int NIN  = 4096;
static constexpr int NOUT = 4096;

// ==================== GEMM tiling ====================
static constexpr int BM = 128;
static constexpr int BN = 128;
static constexpr int BK = 128;            // fp8 elements of K per stage
static constexpr int STAGES = 3;
static constexpr int KITERS = NIN / BK;   // 32

// smem layout (dynamic)
static constexpr unsigned SM_BARS  = 0;   // full[s] at 8s; empty[s] at 8*(STAGES+s)
static constexpr unsigned SM_SC    = 128;                   // BN floats (scale)
static constexpr unsigned SM_BI    = SM_SC + BN * 4;
static constexpr unsigned SM_TILE0 = 4096;                  // 1024-aligned tiles
static constexpr unsigned A_BYTES     = BM * BK;            // 16384
static constexpr unsigned B_BYTES     = BN * BK;            // 16384
static constexpr unsigned STAGE_BYTES = A_BYTES + B_BYTES;  // 32768
static constexpr unsigned SMEM_TOTAL  = SM_TILE0 + STAGES * STAGE_BYTES; // 102400 (2 CTAs/SM)

static constexpr int MATH_WARPS = 8;
static constexpr int NTHREADS   = (MATH_WARPS + 1) * 32;    // 288: 8 math + 1 producer

// merged prep grid: blocks [0, NOUT) do weight rows; [NOUT, NOUT + XBLOCKS) do x chunks
static constexpr int XBLOCKS = BDIM * NIN / 16 / 256;       // 16384

// ==================== scratch (device globals: no allocs allowed) ====================
__device__ __align__(1024) unsigned char g_xb[(size_t)BDIM * NIN]; // sign(x) as e4m3
__device__ __align__(1024) unsigned char g_wb[(size_t)NOUT * NIN]; // sign(fp-mean) as e4m3
__device__ float g_scale[NOUT];

// ==================== PTX helpers (baseline PTX only) ====================
__device__ __forceinline__ uint32_t smem_to_u32(const void* p) {
    uint32_t a;
    asm("{ .reg .u64 t; cvta.to.shared.u64 t, %1; cvt.u32.u64 %0, t; }" : "=r"(a) : "l"(p));
    return a;
}

// Programmatic dependent launch (baseline sm_90 PTX)
#define GRIDDEP_LAUNCH_DEPENDENTS() asm volatile("griddepcontrol.launch_dependents;" ::: "memory")
#define GRIDDEP_WAIT()              asm volatile("griddepcontrol.wait;" ::: "memory")

#define MBARRIER_INIT(addr, cnt) \
    asm volatile("mbarrier.init.shared.b64 [%0], %1;" :: "r"((uint32_t)(addr)), "r"((uint32_t)(cnt)) : "memory")

#define MBARRIER_ARRIVE(addr) \
    asm volatile("mbarrier.arrive.shared.b64 _, [%0];" :: "r"((uint32_t)(addr)) : "memory")

#define MBARRIER_EXPECT_TX(addr, bytes) \
    asm volatile("mbarrier.arrive.expect_tx.shared.b64 _, [%0], %1;" :: "r"((uint32_t)(addr)), "r"((uint32_t)(bytes)) : "memory")

#define MBARRIER_WAIT_PARITY(mbar_smem_addr, phase_parity) do { \
    uint32_t _mbar = (uint32_t)(mbar_smem_addr); \
    uint32_t _parity = (uint32_t)(phase_parity); \
    uint32_t _done; \
    asm volatile( \
        "{\n\t.reg .pred p;\n\t" \
        "mbarrier.try_wait.parity.acquire.cta.shared::cta.b64 p, [%1], %2;\n\t" \
        "selp.b32 %0, 1, 0, p;\n\t}" \
        : "=r"(_done) : "r"(_mbar), "r"(_parity) : "memory"); \
    if (!_done) { \
        asm volatile( \
            "{\n\t.reg .pred P1;\n\t" \
            "WAIT_LOOP_%=:\n\t" \
            "mbarrier.try_wait.parity.acquire.cta.shared::cta.b64 P1, [%0], %1, 0x989680;\n\t" \
            "@P1 bra.uni WAIT_DONE_%=;\n\t" \
            "bra.uni WAIT_LOOP_%=;\n\t" \
            "WAIT_DONE_%=:\n\t}" \
            :: "r"(_mbar), "r"(_parity) : "memory"); \
    } \
} while (0)

// Relaxed variant: producer-only (post-wait smem accesses are async-proxy TMA).
#define MBARRIER_WAIT_PARITY_RELAXED(mbar_smem_addr, phase_parity) do { \
    uint32_t _mbar = (uint32_t)(mbar_smem_addr); \
    uint32_t _parity = (uint32_t)(phase_parity); \
    uint32_t _done; \
    asm volatile( \
        "{\n\t.reg .pred p;\n\t" \
        "mbarrier.try_wait.parity.relaxed.cta.shared::cta.b64 p, [%1], %2, 0x989680;\n\t" \
        "selp.b32 %0, 1, 0, p;\n\t}" \
        : "=r"(_done) : "r"(_mbar), "r"(_parity) : "memory"); \
    if (!_done) { \
        asm volatile( \
            "{\n\t.reg .pred P1;\n\t" \
            "WAIT_LOOP_%=:\n\t" \
            "mbarrier.try_wait.parity.relaxed.cta.shared::cta.b64 P1, [%0], %1, 0x989680;\n\t" \
            "@P1 bra.uni WAIT_DONE_%=;\n\t" \
            "bra.uni WAIT_LOOP_%=;\n\t" \
            "WAIT_DONE_%=:\n\t}" \
            :: "r"(_mbar), "r"(_parity) : "memory"); \
    } \
} while (0)

#define TMA_LOAD_3D(smem_addr, tensor_map, cx, cy, cz, mbar) \
    asm volatile( \
        "cp.async.bulk.tensor.3d.shared::cta.global.tile.mbarrier::complete_tx::bytes " \
        "[%0], [%1, {%2, %3, %4}], [%5];" \
        :: "r"((uint32_t)(smem_addr)), "l"(tensor_map), "r"((int32_t)(cx)), "r"((int32_t)(cy)), \
           "r"((int32_t)(cz)), "r"((uint32_t)(mbar)) : "memory")

#define FENCE_PROXY_ASYNC_SHARED_CTA() asm volatile("fence.proxy.async.shared::cta;" ::: "memory")

#define LDMATRIX_X4(r0, r1, r2, r3, addr) \
    asm volatile("ldmatrix.sync.aligned.m8n8.x4.shared.b16 {%0,%1,%2,%3}, [%4];" \
                 : "=r"(r0), "=r"(r1), "=r"(r2), "=r"(r3) : "r"(addr))

// legacy FP8 QMMA with F16 accumulator: m16n8k32, e4m3 x e4m3 (sm_89+ baseline).
#define MMA_F8_H(d, a, b) \
    asm volatile("mma.sync.aligned.m16n8k32.row.col.f16.e4m3.e4m3.f16 " \
                 "{%0,%1}, {%2,%3,%4,%5}, {%6,%7}, {%0,%1};" \
                 : "+r"((d)[0]), "+r"((d)[1]) \
                 : "r"((a)[0]), "r"((a)[1]), "r"((a)[2]), "r"((a)[3]), \
                   "r"((b)[0]), "r"((b)[1]))

// ==================== merged prep kernel ====================
// e4m3: +1.0 = 0x38, -1.0 = 0xB8, 0.0 = 0x00
__device__ __forceinline__ uint32_t sgn8(float v) {
    return v > 0.f ? 0x38u : (v < 0.f ? 0xB8u : 0x00u);
}

__device__ __forceinline__ float4 ldcs4(const float4* p) {
    float4 v;
    asm volatile("ld.global.cs.v4.f32 {%0,%1,%2,%3}, [%4];"
                 : "=f"(v.x), "=f"(v.y), "=f"(v.z), "=f"(v.w) : "l"(p));
    return v;
}

// blocks [0, NOUT): one weight row each (center, clamp, sign, scale).
// blocks [NOUT, NOUT+XBLOCKS): 4096-byte x chunks (sign pack).
// Each CTA signals launch_dependents after its stores: the GEMM may start its
// prologue early; its griddepcontrol.wait guarantees these stores are visible.
__global__ void __launch_bounds__(256) prep_all_kernel(const float4* __restrict__ x,
                                                       uint4* __restrict__ xb,
                                                       const float* __restrict__ w,
                                                       uint4* __restrict__ wb,
                                                       float* __restrict__ scale) {
    const int tid = threadIdx.x;
    if (blockIdx.x >= NOUT) {
        // ---- x path ----
        const size_t i = (size_t)(blockIdx.x - NOUT) * 256 + tid;
        uint32_t p[4];
#pragma unroll
        for (int q = 0; q < 4; q++) {
            float4 v = ldcs4(x + i * 4 + q);
            p[q] = sgn8(v.x) | (sgn8(v.y) << 8) | (sgn8(v.z) << 16) | (sgn8(v.w) << 24);
        }
        xb[i] = make_uint4(p[0], p[1], p[2], p[3]);
        GRIDDEP_LAUNCH_DEPENDENTS();
        return;
    }

    // ---- w path ----
    __shared__ float red[256];
    const int row = blockIdx.x;
    const float4* wr = (const float4*)(w + (size_t)row * NIN);

    float4 v[4];
    float s = 0.f;
#pragma unroll
    for (int q = 0; q < 4; q++) {
        v[q] = ldcs4(wr + tid * 4 + q);
        s += (v[q].x + v[q].y) + (v[q].z + v[q].w);
    }
    red[tid] = s;
    __syncthreads();
    for (int o = 128; o > 0; o >>= 1) {
        if (tid < o) red[tid] += red[tid + o];
        __syncthreads();
    }
    const float mean = red[0] * (1.f / NIN);
    __syncthreads();

    float a = 0.f;
    uint32_t p[4];
#pragma unroll
    for (int q = 0; q < 4; q++) {
        float f0 = v[q].x - mean, f1 = v[q].y - mean, f2 = v[q].z - mean, f3 = v[q].w - mean;
        a += fabsf(fminf(fmaxf(f0, -1.f), 1.f));
        a += fabsf(fminf(fmaxf(f1, -1.f), 1.f));
        a += fabsf(fminf(fmaxf(f2, -1.f), 1.f));
        a += fabsf(fminf(fmaxf(f3, -1.f), 1.f));
        p[q] = sgn8(f0) | (sgn8(f1) << 8) | (sgn8(f2) << 16) | (sgn8(f3) << 24);
    }
    wb[(size_t)row * (NIN / 16) + tid] = make_uint4(p[0], p[1], p[2], p[3]);

    red[tid] = a;
    __syncthreads();
    for (int o = 128; o > 0; o >>= 1) {
        if (tid < o) red[tid] += red[tid + o];
        __syncthreads();
    }
    if (tid == 0) scale[row] = red[0] * (1.f / NIN);
    GRIDDEP_LAUNCH_DEPENDENTS();
}

// ==================== GEMM kernel (legacy FP8 QMMA f16-acc, warp-specialized) ====================
// 288 threads: warps 0-7 math (2m x 4n grid, 64x32 warp tile), warp 8 = TMA producer.
// 2 CTAs/SM, N-fast rasterization. Math mainloop byte-identical to the measured
// optimum; PDL: barrier-init prologue overlaps prep's tail, griddepcontrol.wait
// before any dependent data (scale/bias/xb/wb) is touched.
__global__ void __launch_bounds__(NTHREADS, 2)
xnor_gemm_kernel(const __grid_constant__ CUtensorMap tma_a,
                 const __grid_constant__ CUtensorMap tma_b,
                 const float* __restrict__ scale,
                 const float* __restrict__ bias,
                 float* __restrict__ out) {
    extern __shared__ char smem[];
    const uint32_t sb = smem_to_u32(smem);
    const int tid = threadIdx.x;
    const int wid = tid >> 5;
    const int lane = tid & 31;

    const int n0 = blockIdx.x * BN;   // N fastest
    const int m0 = blockIdx.y * BM;

    // prologue that does NOT depend on prep's output: runs during prep's tail
    if (tid == 0) {
#pragma unroll
        for (int s = 0; s < STAGES; s++) {
            MBARRIER_INIT(sb + SM_BARS + 8u * s, 1);                    // full (TMA tx)
            MBARRIER_INIT(sb + SM_BARS + 8u * (STAGES + s), MATH_WARPS); // empty
        }
        FENCE_PROXY_ASYNC_SHARED_CTA();
    }

    // wait for prep grid's stores (xb, wb, scale) to be visible
    GRIDDEP_WAIT();

    // stage scale/bias for this n-tile
    {
        float* s_sc = (float*)(smem + SM_SC);
        float* s_bi = (float*)(smem + SM_BI);
        if (tid < BN) {
            s_sc[tid] = scale[n0 + tid];
            s_bi[tid] = bias[n0 + tid];
        }
    }
    __syncthreads();  // barriers initialized + scale/bias visible

    if (wid == MATH_WARPS) {
        // ================= producer warp =================
        if (lane == 0) {
#pragma unroll
            for (int p = 0; p < STAGES; p++) {
                MBARRIER_EXPECT_TX(sb + SM_BARS + 8u * p, STAGE_BYTES);
                const uint32_t st = sb + SM_TILE0 + (uint32_t)p * STAGE_BYTES;
                TMA_LOAD_3D(st, &tma_a, p * BK, m0, 0, sb + SM_BARS + 8u * p);
                TMA_LOAD_3D(st + A_BYTES, &tma_b, p * BK, n0, 0, sb + SM_BARS + 8u * p);
            }
            int s = 0, eph = 0;
            for (int ld = STAGES; ld < KITERS; ++ld) {
                MBARRIER_WAIT_PARITY_RELAXED(sb + SM_BARS + 8u * (STAGES + s), eph);
                MBARRIER_EXPECT_TX(sb + SM_BARS + 8u * s, STAGE_BYTES);
                const uint32_t st = sb + SM_TILE0 + (uint32_t)s * STAGE_BYTES;
                TMA_LOAD_3D(st, &tma_a, ld * BK, m0, 0, sb + SM_BARS + 8u * s);
                TMA_LOAD_3D(st + A_BYTES, &tma_b, ld * BK, n0, 0, sb + SM_BARS + 8u * s);
                if (++s == STAGES) { s = 0; eph ^= 1; }
            }
        }
        return;
    }

    // ================= math warps =================
    const int warp_m = wid & 1;   // 0..1  (64 rows each)
    const int warp_n = wid >> 1;  // 0..3  (32 cols each)
    const int rlo = lane & 7;
    const int sub = (lane >> 3) & 3;

    // precomputed ldmatrix offsets (SW128: phys = row*128 + (kbyte ^ ((row&7)<<4)))
    uint32_t aRow[4], bRow[2], kx[4];
#pragma unroll
    for (int im = 0; im < 4; im++)
        aRow[im] = (uint32_t)(warp_m * 64 + im * 16 + (sub & 1) * 8 + rlo) * 128u;
#pragma unroll
    for (int bp = 0; bp < 2; bp++)
        bRow[bp] = (uint32_t)(warp_n * 32 + bp * 16 + (sub & 1) * 8 + rlo) * 128u;
#pragma unroll
    for (int ks = 0; ks < 4; ks++)
        kx[ks] = (uint32_t)((ks * 32 + ((sub >> 1) & 1) * 16) ^ (rlo << 4));

    // f16x2 accumulators (exact: |partial sums| << 2048)
    uint32_t d[4][4][2];
#pragma unroll
    for (int im = 0; im < 4; im++)
#pragma unroll
        for (int in = 0; in < 4; in++) { d[im][in][0] = 0u; d[im][in][1] = 0u; }

    int s = 0, ph = 0;
    for (int it = 0; it < KITERS; ++it) {
        MBARRIER_WAIT_PARITY(sb + SM_BARS + 8u * s, ph);
        const uint32_t saA = sb + SM_TILE0 + (uint32_t)s * STAGE_BYTES;
        const uint32_t saB = saA + A_BYTES;

#pragma unroll
        for (int ks = 0; ks < 4; ks++) {
            uint32_t a[4][4];
            uint32_t b[4][2];
#pragma unroll
            for (int im = 0; im < 4; im++) {
                LDMATRIX_X4(a[im][0], a[im][1], a[im][2], a[im][3], saA + aRow[im] + kx[ks]);
            }
#pragma unroll
            for (int bp = 0; bp < 2; bp++) {
                uint32_t r0, r1, r2, r3;
                LDMATRIX_X4(r0, r1, r2, r3, saB + bRow[bp] + kx[ks]);
                b[2 * bp][0] = r0; b[2 * bp + 1][0] = r1;
                b[2 * bp][1] = r2; b[2 * bp + 1][1] = r3;
            }
#pragma unroll
            for (int im = 0; im < 4; im++)
#pragma unroll
                for (int in = 0; in < 4; in++) MMA_F8_H(d[im][in], a[im], b[in]);
        }

        if (lane == 0) MBARRIER_ARRIVE(sb + SM_BARS + 8u * (STAGES + s));
        if (++s == STAGES) { s = 0; ph ^= 1; }
    }

    // -------- epilogue: out = float(acc) * scale[n] + bias[n] --------
    const float* s_sc = (const float*)(smem + SM_SC);
    const float* s_bi = (const float*)(smem + SM_BI);
    const int gm0 = m0 + warp_m * 64 + (lane >> 2);
    const int lc0 = warp_n * 32 + (lane & 3) * 2;

#pragma unroll
    for (int im = 0; im < 4; im++) {
#pragma unroll
        for (int in = 0; in < 4; in++) {
            const int lc = lc0 + in * 8;
            const float sc0 = s_sc[lc], sc1 = s_sc[lc + 1];
            const float bi0 = s_bi[lc], bi1 = s_bi[lc + 1];
            const int row0 = gm0 + im * 16;
            const float2 lo = __half22float2(*reinterpret_cast<const __half2*>(&d[im][in][0]));
            const float2 hi = __half22float2(*reinterpret_cast<const __half2*>(&d[im][in][1]));
            float2 v0, v1;
            v0.x = lo.x * sc0 + bi0;
            v0.y = lo.y * sc1 + bi1;
            v1.x = hi.x * sc0 + bi0;
            v1.y = hi.y * sc1 + bi1;
            *reinterpret_cast<float2*>(out + (size_t)row0 * NOUT + n0 + lc) = v0;
            *reinterpret_cast<float2*>(out + (size_t)(row0 + 8) * NOUT + n0 + lc) = v1;
        }
    }
}

// ==================== host launch ====================
typedef CUresult (*TMEncodeFn)(CUtensorMap*, CUtensorMapDataType, cuuint32_t, void*,
                               const cuuint64_t*, const cuuint64_t*, const cuuint32_t*,
                               const cuuint32_t*, CUtensorMapInterleave, CUtensorMapSwizzle,
                               CUtensorMapL2promotion, CUtensorMapFloatOOBfill);

extern "C" void kernel_launch(void* const* d_in, const int* in_sizes, int n_in,
                              void* d_out, int out_size) {
    const float* x    = (const float*)d_in[0];
    const float* fp   = (const float*)d_in[1];
    const float* bias = (const float*)d_in[2];
    float* out = (float*)d_out;

    void *xb = nullptr, *wb = nullptr, *scale = nullptr;
    cudaGetSymbolAddress(&xb, g_xb);
    cudaGetSymbolAddress(&wb, g_wb);
    cudaGetSymbolAddress(&scale, g_scale);

    // merged preprocessing: w-rows (blocks 0..4095) + x-chunks (blocks 4096..20479)
    prep_all_kernel<<<NOUT + XBLOCKS, 256>>>((const float4*)x, (uint4*)xb,
                                             fp, (uint4*)wb, (float*)scale);

    // TMA descriptors (driver entry point via runtime — no -lcuda needed)
    TMEncodeFn enc = nullptr;
    cudaDriverEntryPointQueryResult qr;
    cudaGetDriverEntryPoint("cuTensorMapEncodeTiled", (void**)&enc, cudaEnableDefault, &qr);

    CUtensorMap ta, tb;
    cuuint32_t es[3] = {1, 1, 1};
    {
        cuuint64_t dims[3] = {NIN, BDIM, 1};
        cuuint64_t str[2]  = {NIN, (cuuint64_t)NIN * BDIM};
        cuuint32_t box[3]  = {BK, BM, 1};
        enc(&ta, CU_TENSOR_MAP_DATA_TYPE_UINT8, 3, xb, dims, str, box, es,
            CU_TENSOR_MAP_INTERLEAVE_NONE, CU_TENSOR_MAP_SWIZZLE_128B,
            CU_TENSOR_MAP_L2_PROMOTION_L2_128B, CU_TENSOR_MAP_FLOAT_OOB_FILL_NONE);
    }
    {
        cuuint64_t dims[3] = {NIN, NOUT, 1};
        cuuint64_t str[2]  = {NIN, (cuuint64_t)NIN * NOUT};
        cuuint32_t box[3]  = {BK, BN, 1};
        enc(&tb, CU_TENSOR_MAP_DATA_TYPE_UINT8, 3, wb, dims, str, box, es,
            CU_TENSOR_MAP_INTERLEAVE_NONE, CU_TENSOR_MAP_SWIZZLE_128B,
            CU_TENSOR_MAP_L2_PROMOTION_L2_128B, CU_TENSOR_MAP_FLOAT_OOB_FILL_NONE);
    }

    cudaFuncSetAttribute(xnor_gemm_kernel, cudaFuncAttributeMaxDynamicSharedMemorySize,
                         SMEM_TOTAL);

    // GEMM launch with programmatic dependent launch: overlaps its prologue with
    // prep's tail; device-side griddepcontrol.wait provides the data dependency.
    cudaLaunchConfig_t cfg = {};
    cfg.gridDim = dim3(NOUT / BN, BDIM / BM, 1);   // x = N-tiles (fast), y = M-tiles
    cfg.blockDim = dim3(NTHREADS, 1, 1);
    cfg.dynamicSmemBytes = SMEM_TOTAL;
    cudaLaunchAttribute attrs[1];
    attrs[0].id = cudaLaunchAttributeProgrammaticStreamSerialization;
    attrs[0].val.programmaticStreamSerializationAllowed = 1;
    cfg.attrs = attrs;
    cfg.numAttrs = 1;
    cudaLaunchKernelEx(&cfg, xnor_gemm_kernel, ta, tb,
                       (const float*)scale, (const float*)bias, out);
}